// round 4
// baseline (speedup 1.0000x reference)
#include <cuda_runtime.h>
#include <cuda_bf16.h>
#include <math.h>
#include <stdint.h>

// Problem constants
#define NB    1024      // bs*T
#define NAG   16
#define HYPD  256
#define NROWS 65536     // NB*64

// ---------------- scratch (device globals; no allocation) ----------------
// packed bf16x2 (hi/lo split) operand storage
__device__ uint32_t g_ehi[4194304],  g_elo[4194304];    // entities  [65536,128]
__device__ uint32_t g_whi[589824],   g_wlo[589824];     // all weights, 4 params
__device__ uint32_t g_x1h[33554432], g_x1l[33554432];   // x1 [4][65536,256]
__device__ uint32_t g_ath[8388608],  g_atl[8388608];    // attn [4][16384,256]
__device__ float    g_qkv[201326592ull];                // [4][65536,768] fp32
__device__ float    g_a2 [16777216];                    // [4][16384,256] fp32
__device__ float    g_w1mat[(size_t)NB * NAG * 32];
__device__ float    g_b1vec[(size_t)NB * 32];
__device__ float    g_wfvec[(size_t)NB * 32];
__device__ float    g_vvs  [NB];

// ================= helpers ================================================
__device__ __forceinline__ uint32_t smem_u32(const void* p) {
    uint32_t a;
    asm("{ .reg .u64 t; cvta.to.shared.u64 t, %1; cvt.u32.u64 %0, t; }"
        : "=r"(a) : "l"(p));
    return a;
}

// fp32 pair -> packed bf16x2 (hi) + packed bf16x2 (residual lo)
__device__ __forceinline__ void cvt_pair(float a, float b, uint32_t& hi, uint32_t& lo) {
    asm("cvt.rn.bf16x2.f32 %0, %1, %2;" : "=r"(hi) : "f"(b), "f"(a)); // low16=a
    float ra = a - __uint_as_float(hi << 16);
    float rb = b - __uint_as_float(hi & 0xffff0000u);
    asm("cvt.rn.bf16x2.f32 %0, %1, %2;" : "=r"(lo) : "f"(rb), "f"(ra));
}

__device__ __forceinline__ void ldm_x4(uint32_t* r, uint32_t addr) {
    asm volatile("ldmatrix.sync.aligned.m8n8.x4.shared.b16 {%0,%1,%2,%3}, [%4];"
                 : "=r"(r[0]), "=r"(r[1]), "=r"(r[2]), "=r"(r[3]) : "r"(addr));
}

__device__ __forceinline__ void mma_bf16(float* d, const uint32_t* a,
                                         uint32_t b0, uint32_t b1) {
    asm volatile(
        "mma.sync.aligned.m16n8k16.row.col.f32.bf16.bf16.f32 "
        "{%0,%1,%2,%3},{%4,%5,%6,%7},{%8,%9},{%0,%1,%2,%3};"
        : "+f"(d[0]), "+f"(d[1]), "+f"(d[2]), "+f"(d[3])
        : "r"(a[0]), "r"(a[1]), "r"(a[2]), "r"(a[3]), "r"(b0), "r"(b1));
}

#define CP16(d, s)  asm volatile("cp.async.cg.shared.global [%0], [%1], 16;" \
                                 :: "r"(d), "l"(s) : "memory")
#define CPCOMMIT()  asm volatile("cp.async.commit_group;" ::: "memory")
#define CPWAIT1()   asm volatile("cp.async.wait_group 1;" ::: "memory")

// =============== split prep: fp32 -> bf16 hi/lo arrays ====================
struct SplitTable {
    const float* src[13];
    uint32_t*    hi [13];
    uint32_t*    lo [13];
    int          cum[14];   // cumulative block counts
};

__global__ __launch_bounds__(256) void split_all(SplitTable t)
{
    const int bx = blockIdx.x;
    int e = 0;
#pragma unroll
    for (int i = 1; i < 13; i++) if (bx >= t.cum[i]) e = i;
    const int idx4 = (bx - t.cum[e]) * 256 + threadIdx.x;  // float4 index
    float4 v = reinterpret_cast<const float4*>(t.src[e])[idx4];
    uint32_t h0, l0, h1, l1;
    cvt_pair(v.x, v.y, h0, l0);
    cvt_pair(v.z, v.w, h1, l1);
    reinterpret_cast<uint2*>(t.hi[e])[idx4] = make_uint2(h0, h1);
    reinterpret_cast<uint2*>(t.lo[e])[idx4] = make_uint2(l0, l1);
}

// =============== batched tensor-core GEMM =================================
// C_z[M,N] = A_z[M,K] @ B_z[N,K]^T (+bias)(+relu).
// A, B pre-split bf16 hi/lo in gmem (packed u32 pairs). 3-MMA compensated.
// CTA tile 128x128, Ktile 32, cp.async 2-stage pipeline, 16 warps (4x4).
struct GemmBatch {
    const uint32_t *Ahi[4], *Alo[4], *Bhi[4], *Blo[4];
    const float*    bias[4];
    float*          C[4];
    uint32_t       *Chi[4], *Clo[4];
};

#define SROW       80
#define TILE       (128 * SROW)     // 10240
#define BUF        (4 * TILE)       // 40960
#define GEMM_SMEM  (2 * BUF)        // 81920

__global__ void __launch_bounds__(512, 1)
gemm_mma(GemmBatch args, int N, int K, int relu, int osplit)
{
    extern __shared__ char smem[];
    const int z    = blockIdx.z;
    const int tid  = threadIdx.x;
    const int lane = tid & 31;
    const int wid  = tid >> 5;
    const int wm   = wid & 3;       // warp row (4)
    const int wn   = wid >> 2;      // warp col (4)
    const uint32_t sbase = smem_u32(smem);

    // loader: each thread owns one 16B chunk per tile (row, kc)
    const int row = tid >> 2;
    const int kc  = tid & 3;
    const char* srcAh = (const char*)args.Ahi[z] + ((size_t)(blockIdx.y * 128 + row) * K + kc * 8) * 2;
    const char* srcAl = (const char*)args.Alo[z] + ((size_t)(blockIdx.y * 128 + row) * K + kc * 8) * 2;
    const char* srcBh = (const char*)args.Bhi[z] + ((size_t)(blockIdx.x * 128 + row) * K + kc * 8) * 2;
    const char* srcBl = (const char*)args.Blo[z] + ((size_t)(blockIdx.x * 128 + row) * K + kc * 8) * 2;
    const uint32_t dstb = sbase + row * SROW + kc * 16;

    float acc[2][4][4];
#pragma unroll
    for (int a = 0; a < 2; a++)
#pragma unroll
        for (int b = 0; b < 4; b++)
#pragma unroll
            for (int c = 0; c < 4; c++) acc[a][b][c] = 0.f;

    const int nk = K >> 5;

#define ISSUE(kt, b) do {                                    \
        const uint32_t _d = dstb + (b) * BUF;                \
        const size_t _o = (size_t)(kt) * 64;                 \
        CP16(_d,            srcAh + _o);                     \
        CP16(_d + TILE,     srcAl + _o);                     \
        CP16(_d + 2 * TILE, srcBh + _o);                     \
        CP16(_d + 3 * TILE, srcBl + _o);                     \
    } while (0)

    ISSUE(0, 0); CPCOMMIT();
    ISSUE(1, 1); CPCOMMIT();

    const int lrow  = lane & 15;
    const int khalf = lane >> 4;

    for (int kt = 0; kt < nk; kt++) {
        const int b = kt & 1;
        CPWAIT1();
        __syncthreads();
        const uint32_t sA  = sbase + b * BUF;
        const uint32_t sAl = sA + TILE;
        const uint32_t sB  = sA + 2 * TILE;
        const uint32_t sBl = sA + 3 * TILE;
#pragma unroll
        for (int ks = 0; ks < 2; ks++) {
            const uint32_t koff = ks * 32 + khalf * 16;
            uint32_t ah[2][4], bh[2][4];
#pragma unroll
            for (int mb = 0; mb < 2; mb++)
                ldm_x4(ah[mb], sA + (wm * 32 + mb * 16 + lrow) * SROW + koff);
#pragma unroll
            for (int nbb = 0; nbb < 2; nbb++)
                ldm_x4(bh[nbb], sB + (wn * 32 + nbb * 16 + lrow) * SROW + koff);
#pragma unroll
            for (int mb = 0; mb < 2; mb++)
#pragma unroll
                for (int nb = 0; nb < 4; nb++)
                    mma_bf16(acc[mb][nb], ah[mb],
                             bh[nb >> 1][nb & 1], bh[nb >> 1][(nb & 1) + 2]);
            uint32_t bl[2][4];
#pragma unroll
            for (int nbb = 0; nbb < 2; nbb++)
                ldm_x4(bl[nbb], sBl + (wn * 32 + nbb * 16 + lrow) * SROW + koff);
#pragma unroll
            for (int mb = 0; mb < 2; mb++)
#pragma unroll
                for (int nb = 0; nb < 4; nb++)
                    mma_bf16(acc[mb][nb], ah[mb],
                             bl[nb >> 1][nb & 1], bl[nb >> 1][(nb & 1) + 2]);
            uint32_t al[2][4];
#pragma unroll
            for (int mb = 0; mb < 2; mb++)
                ldm_x4(al[mb], sAl + (wm * 32 + mb * 16 + lrow) * SROW + koff);
#pragma unroll
            for (int mb = 0; mb < 2; mb++)
#pragma unroll
                for (int nb = 0; nb < 4; nb++)
                    mma_bf16(acc[mb][nb], al[mb],
                             bh[nb >> 1][nb & 1], bh[nb >> 1][(nb & 1) + 2]);
        }
        __syncthreads();
        if (kt + 2 < nk) ISSUE(kt + 2, b);
        CPCOMMIT();
    }
#undef ISSUE

    // epilogue
    const int r0 = blockIdx.y * 128 + wm * 32 + (lane >> 2);
    const int c0 = blockIdx.x * 128 + wn * 32 + (lane & 3) * 2;
    const float* bias = args.bias[z];
#pragma unroll
    for (int nb = 0; nb < 4; nb++) {
        const int col = c0 + nb * 8;
        const float b0 = bias ? bias[col]     : 0.f;
        const float b1 = bias ? bias[col + 1] : 0.f;
#pragma unroll
        for (int mb = 0; mb < 2; mb++) {
            float v0 = acc[mb][nb][0] + b0;
            float v1 = acc[mb][nb][1] + b1;
            float v2 = acc[mb][nb][2] + b0;
            float v3 = acc[mb][nb][3] + b1;
            if (relu) {
                v0 = fmaxf(v0, 0.f); v1 = fmaxf(v1, 0.f);
                v2 = fmaxf(v2, 0.f); v3 = fmaxf(v3, 0.f);
            }
            const int r = r0 + mb * 16;
            if (!osplit) {
                *reinterpret_cast<float2*>(args.C[z] + (size_t)r * N + col)       = make_float2(v0, v1);
                *reinterpret_cast<float2*>(args.C[z] + (size_t)(r + 8) * N + col) = make_float2(v2, v3);
            } else {
                uint32_t hu, lu;
                cvt_pair(v0, v1, hu, lu);
                args.Chi[z][((size_t)r * N + col) >> 1] = hu;
                args.Clo[z][((size_t)r * N + col) >> 1] = lu;
                cvt_pair(v2, v3, hu, lu);
                args.Chi[z][((size_t)(r + 8) * N + col) >> 1] = hu;
                args.Clo[z][((size_t)(r + 8) * N + col) >> 1] = lu;
            }
        }
    }
}

// ---------------- per-row attention (1 CTA per (batch row, param)) --------
// Consumes qkv fp32, writes attn output pre-split (hi/lo bf16).
struct AttnBatch { const float* qkv[4]; uint32_t* ahi[4]; uint32_t* alo[4]; };

__global__ __launch_bounds__(256)
void attn_kernel(AttnBatch args, const int* __restrict__ emask)
{
    __shared__ float Qs[16][64];
    __shared__ float Kt[64][68];
    __shared__ float Vs[64][64];
    __shared__ float Ws[16][68];
    __shared__ int   em[64];

    const int b   = blockIdx.x;
    const int z   = blockIdx.z;
    const int tid = threadIdx.x;
    const float* __restrict__ qkv = args.qkv[z];
    uint32_t* __restrict__ ahi    = args.ahi[z];
    uint32_t* __restrict__ alo    = args.alo[z];

    if (tid < 64) em[tid] = emask[b * 64 + tid];
    const float* qb = qkv + (size_t)b * 64 * 768;

    for (int hh = 0; hh < 4; ++hh) {
        __syncthreads();
        {
            int n  = tid >> 4;
            int d0 = (tid & 15) << 2;
            *reinterpret_cast<float4*>(&Qs[n][d0]) =
                *reinterpret_cast<const float4*>(qb + (size_t)n * 768 + hh * 64 + d0);
        }
        {
            int n  = tid >> 2;
            int d0 = (tid & 3) << 4;
            const float* kr = qb + (size_t)n * 768 + 256 + hh * 64 + d0;
            const float* vr = qb + (size_t)n * 768 + 512 + hh * 64 + d0;
#pragma unroll
            for (int j = 0; j < 4; j++) {
                float4 kv = *reinterpret_cast<const float4*>(kr + j * 4);
                Kt[d0 + j*4 + 0][n] = kv.x; Kt[d0 + j*4 + 1][n] = kv.y;
                Kt[d0 + j*4 + 2][n] = kv.z; Kt[d0 + j*4 + 3][n] = kv.w;
                *reinterpret_cast<float4*>(&Vs[n][d0 + j*4]) =
                    *reinterpret_cast<const float4*>(vr + j * 4);
            }
        }
        __syncthreads();
        {
            int qi = tid >> 4;
            int k0 = (tid & 15) << 2;
            float4 acc = make_float4(0.f, 0.f, 0.f, 0.f);
#pragma unroll 8
            for (int d = 0; d < 64; ++d) {
                float  qv = Qs[qi][d];
                float4 kv = *reinterpret_cast<const float4*>(&Kt[d][k0]);
                acc.x += qv * kv.x; acc.y += qv * kv.y;
                acc.z += qv * kv.z; acc.w += qv * kv.w;
            }
            int   amq  = em[qi];
            float lg[4] = {acc.x, acc.y, acc.z, acc.w};
#pragma unroll
            for (int j = 0; j < 4; j++) {
                int kk = k0 + j;
                bool valid = (amq == 0) && (em[kk] == 0);
                Ws[qi][kk] = valid ? lg[j] * 0.125f : -1e30f;
            }
        }
        __syncthreads();
        {
            int w = tid >> 5, lane = tid & 31;
            for (int r = 0; r < 2; r++) {
                int   qi = w * 2 + r;
                float v0 = Ws[qi][lane], v1 = Ws[qi][lane + 32];
                float m  = fmaxf(v0, v1);
                for (int off = 16; off; off >>= 1)
                    m = fmaxf(m, __shfl_xor_sync(0xffffffffu, m, off));
                float e0 = 0.f, e1 = 0.f, s = 1.f;
                if (m > -1e29f) {
                    e0 = expf(v0 - m); e1 = expf(v1 - m);
                    s = e0 + e1;
                    for (int off = 16; off; off >>= 1)
                        s += __shfl_xor_sync(0xffffffffu, s, off);
                }
                float inv = 1.f / s;
                Ws[qi][lane]      = e0 * inv;
                Ws[qi][lane + 32] = e1 * inv;
            }
        }
        __syncthreads();
        {
            int qi = tid >> 4;
            int d0 = (tid & 15) << 2;
            float4 acc = make_float4(0.f, 0.f, 0.f, 0.f);
#pragma unroll 8
            for (int k = 0; k < 64; k++) {
                float  wv = Ws[qi][k];
                float4 vv = *reinterpret_cast<const float4*>(&Vs[k][d0]);
                acc.x += wv * vv.x; acc.y += wv * vv.y;
                acc.z += wv * vv.z; acc.w += wv * vv.w;
            }
            const size_t e = ((size_t)b * 16 + qi) * 256 + hh * 64 + d0;
            uint32_t h0, l0, h1, l1;
            cvt_pair(acc.x, acc.y, h0, l0);
            cvt_pair(acc.z, acc.w, h1, l1);
            *reinterpret_cast<uint2*>(ahi + (e >> 1)) = make_uint2(h0, h1);
            *reinterpret_cast<uint2*>(alo + (e >> 1)) = make_uint2(l0, l1);
        }
    }
}

// --------- fc2 + agent-mask + mode reduction (z = mode = param set) -------
struct Fc2Batch { const float* a2[4]; const float* w[4]; const float* bvec[4]; };

__global__ __launch_bounds__(256)
void fc2_reduce(Fc2Batch args, const int* __restrict__ emask)
{
    __shared__ float a2s[16][260];
    __shared__ float red[32][17];
    __shared__ float vecs[32];
    const int b    = blockIdx.x;
    const int mode = blockIdx.z;
    const int tid  = threadIdx.x;
    const float* __restrict__ a2   = args.a2[mode];
    const float* __restrict__ fc2w = args.w[mode];
    const float* __restrict__ fc2b = args.bvec[mode];

    for (int i = tid; i < 1024; i += 256) {
        int a  = i >> 6;
        int c4 = (i & 63) << 2;
        *reinterpret_cast<float4*>(&a2s[a][c4]) =
            *reinterpret_cast<const float4*>(a2 + ((size_t)b * 16 + a) * 256 + c4);
    }
    __syncthreads();

    float x3v[2];
#pragma unroll
    for (int it = 0; it < 2; ++it) {
        int o = tid + it * 256;
        int a = o & 15;
        int e = o >> 4;
        float s = 0.f;
        if (emask[b * 64 + a] == 0) {
            const float* wr = fc2w + e * 256;
            float acc = 0.f;
#pragma unroll 4
            for (int kk = 0; kk < 256; ++kk) acc += a2s[a][kk] * wr[kk];
            s = acc + fc2b[e];
        }
        x3v[it] = s;
        if (mode == 0)
            g_w1mat[((size_t)b * 16 + a) * 32 + e] = fabsf(s);
    }
    if (mode != 0) {
#pragma unroll
        for (int it = 0; it < 2; ++it) {
            int o = tid + it * 256;
            red[o >> 4][o & 15] = x3v[it];
        }
        __syncthreads();
        if (tid < 32) {
            float s = 0.f;
#pragma unroll
            for (int a = 0; a < 16; a++) s += red[tid][a];
            s *= (1.f / 16.f);
            vecs[tid] = s;
            if (mode == 1)      g_b1vec[b * 32 + tid] = s;
            else if (mode == 2) g_wfvec[b * 32 + tid] = s;
        }
        __syncthreads();
        if (mode == 3 && tid == 0) {
            float s = 0.f;
            for (int e = 0; e < 32; e++) s += vecs[e];
            g_vvs[b] = s * (1.f / 32.f);
        }
    }
}

// ---------------- final mixing: 1 warp per batch row ----------------------
__global__ __launch_bounds__(256)
void mix_kernel(const float* __restrict__ qs, float* __restrict__ out)
{
    int tid = threadIdx.x;
    int b   = blockIdx.x * 8 + (tid >> 5);
    int e   = tid & 31;
    float h = g_b1vec[b * 32 + e];
#pragma unroll
    for (int a = 0; a < 16; a++)
        h += qs[b * 16 + a] * fabsf(g_w1mat[((size_t)b * 16 + a) * 32 + e]);
    h = h > 0.f ? h : expm1f(h);
    float val = h * fabsf(g_wfvec[b * 32 + e]);
    for (int off = 16; off; off >>= 1)
        val += __shfl_xor_sync(0xffffffffu, val, off);
    if (e == 0) out[b] = val + g_vvs[b];
}

// ---------------- launch --------------------------------------------------
extern "C" void kernel_launch(void* const* d_in, const int* in_sizes, int n_in,
                              void* d_out, int out_size)
{
    (void)in_sizes; (void)n_in; (void)out_size;
    const float* qs    = (const float*)d_in[0];
    const float* ents  = (const float*)d_in[1];
    const int*   emask = (const int*)d_in[2];

    uint32_t *ehi, *elo, *whi, *wlo, *x1h, *x1l, *ath, *atl;
    float *qkv, *a2;
    cudaGetSymbolAddress((void**)&ehi, g_ehi);
    cudaGetSymbolAddress((void**)&elo, g_elo);
    cudaGetSymbolAddress((void**)&whi, g_whi);
    cudaGetSymbolAddress((void**)&wlo, g_wlo);
    cudaGetSymbolAddress((void**)&x1h, g_x1h);
    cudaGetSymbolAddress((void**)&x1l, g_x1l);
    cudaGetSymbolAddress((void**)&ath, g_ath);
    cudaGetSymbolAddress((void**)&atl, g_atl);
    cudaGetSymbolAddress((void**)&qkv, g_qkv);
    cudaGetSymbolAddress((void**)&a2,  g_a2);

    cudaFuncSetAttribute(gemm_mma, cudaFuncAttributeMaxDynamicSharedMemorySize, GEMM_SMEM);

    // ---- split table: entities + 12 weight matrices ----
    // weight pool layout per param: fc1w(32768) qkvw(196608) outw(65536)
    SplitTable st;
    GemmBatch g1, g2, g3;
    AttnBatch ab;
    Fc2Batch  fb;

    st.src[0] = ents; st.hi[0] = ehi; st.lo[0] = elo;
    int cum = 0;
    st.cum[0] = 0;
    cum += 8192; st.cum[1] = cum;                      // entities: 8.4M elems
    const int wsz[3]  = { 32768, 196608, 65536 };
    const int wblk[3] = { 32, 192, 64 };
    for (int p = 0; p < 4; p++) {
        const float* fc1w = (const float*)d_in[3 + 7*p + 0];
        const float* fc1b = (const float*)d_in[3 + 7*p + 1];
        const float* qkvw = (const float*)d_in[3 + 7*p + 2];
        const float* outw = (const float*)d_in[3 + 7*p + 3];
        const float* outb = (const float*)d_in[3 + 7*p + 4];
        const float* fc2w = (const float*)d_in[3 + 7*p + 5];
        const float* fc2b = (const float*)d_in[3 + 7*p + 6];

        const size_t wbase = (size_t)p * 294912;       // elements
        const float* wsrc[3] = { fc1w, qkvw, outw };
        size_t off = wbase;
        for (int j = 0; j < 3; j++) {
            int e = 1 + p * 3 + j;
            st.src[e] = wsrc[j];
            st.hi[e]  = whi + (off >> 1);
            st.lo[e]  = wlo + (off >> 1);
            cum += wblk[j]; st.cum[e + 1] = cum;
            off += wsz[j];
        }

        uint32_t* fc1w_h = whi + (wbase >> 1);
        uint32_t* fc1w_l = wlo + (wbase >> 1);
        uint32_t* qkvw_h = whi + ((wbase + 32768) >> 1);
        uint32_t* qkvw_l = wlo + ((wbase + 32768) >> 1);
        uint32_t* outw_h = whi + ((wbase + 229376) >> 1);
        uint32_t* outw_l = wlo + ((wbase + 229376) >> 1);

        uint32_t* x1hp = x1h + (size_t)p * 8388608;
        uint32_t* x1lp = x1l + (size_t)p * 8388608;
        uint32_t* athp = ath + (size_t)p * 2097152;
        uint32_t* atlp = atl + (size_t)p * 2097152;
        float*    qkvp = qkv + (size_t)p * 50331648;
        float*    a2p  = a2  + (size_t)p * 4194304;

        // fc1: A = entities split, B = fc1w split, out split -> x1
        g1.Ahi[p] = ehi;  g1.Alo[p] = elo;
        g1.Bhi[p] = fc1w_h; g1.Blo[p] = fc1w_l;
        g1.bias[p] = fc1b; g1.C[p] = nullptr;
        g1.Chi[p] = x1hp; g1.Clo[p] = x1lp;
        // qkv: A = x1 split, B = qkvw split, out fp32
        g2.Ahi[p] = x1hp; g2.Alo[p] = x1lp;
        g2.Bhi[p] = qkvw_h; g2.Blo[p] = qkvw_l;
        g2.bias[p] = nullptr; g2.C[p] = qkvp;
        g2.Chi[p] = nullptr; g2.Clo[p] = nullptr;
        // out-proj: A = attn split, B = outw split, out fp32
        g3.Ahi[p] = athp; g3.Alo[p] = atlp;
        g3.Bhi[p] = outw_h; g3.Blo[p] = outw_l;
        g3.bias[p] = outb; g3.C[p] = a2p;
        g3.Chi[p] = nullptr; g3.Clo[p] = nullptr;

        ab.qkv[p] = qkvp; ab.ahi[p] = athp; ab.alo[p] = atlp;
        fb.a2[p] = a2p;   fb.w[p] = fc2w;   fb.bvec[p] = fc2b;
    }

    // prep: split entities + all weights to bf16 hi/lo
    split_all<<<cum, 256>>>(st);
    // fc1:  x1 = relu(E @ fc1^T + b)   [65536, 256], K=128
    gemm_mma<<<dim3(2, 512, 4), 512, GEMM_SMEM>>>(g1, 256, 128, 1, 1);
    // qkv = x1 @ qkv_w^T               [65536, 768], K=256
    gemm_mma<<<dim3(6, 512, 4), 512, GEMM_SMEM>>>(g2, 768, 256, 0, 0);
    // attention -> split attn           [16384, 256] per param
    attn_kernel<<<dim3(NB, 1, 4), 256>>>(ab, emask);
    // a2 = attn @ out_w^T + out_b       [16384, 256], K=256
    gemm_mma<<<dim3(2, 128, 4), 512, GEMM_SMEM>>>(g3, 256, 256, 0, 0);
    // fc2 + mask + mode reductions
    fc2_reduce<<<dim3(NB, 1, 4), 256>>>(fb, emask);
    mix_kernel<<<NB / 8, 256>>>(qs, (float*)d_out);
}

// round 5
// speedup vs baseline: 1.0046x; 1.0046x over previous
#include <cuda_runtime.h>
#include <cuda_bf16.h>
#include <math.h>
#include <stdint.h>

// Problem constants
#define NB    1024      // bs*T
#define NAG   16
#define HYPD  256
#define NROWS 65536     // NB*64

// ---------------- scratch (device globals; no allocation) ----------------
// packed bf16x2 (hi/lo split) operand storage
__device__ uint32_t g_ehi[4194304],  g_elo[4194304];    // entities  [65536,128]
__device__ uint32_t g_whi[589824],   g_wlo[589824];     // all weights, 4 params
__device__ uint32_t g_x1h[33554432], g_x1l[33554432];   // x1 [4][65536,256]
__device__ uint32_t g_ath[8388608],  g_atl[8388608];    // attn [4][16384,256]
__device__ float    g_qkv[201326592ull];                // [4][65536,768] fp32
__device__ float    g_a2 [16777216];                    // [4][16384,256] fp32
__device__ float    g_w1mat[(size_t)NB * NAG * 32];
__device__ float    g_b1vec[(size_t)NB * 32];
__device__ float    g_wfvec[(size_t)NB * 32];
__device__ float    g_vvs  [NB];

// ================= helpers ================================================
__device__ __forceinline__ uint32_t smem_u32(const void* p) {
    uint32_t a;
    asm("{ .reg .u64 t; cvta.to.shared.u64 t, %1; cvt.u32.u64 %0, t; }"
        : "=r"(a) : "l"(p));
    return a;
}

// fp32 pair -> packed bf16x2 (hi) + packed bf16x2 (residual lo)
__device__ __forceinline__ void cvt_pair(float a, float b, uint32_t& hi, uint32_t& lo) {
    asm("cvt.rn.bf16x2.f32 %0, %1, %2;" : "=r"(hi) : "f"(b), "f"(a)); // low16=a
    float ra = a - __uint_as_float(hi << 16);
    float rb = b - __uint_as_float(hi & 0xffff0000u);
    asm("cvt.rn.bf16x2.f32 %0, %1, %2;" : "=r"(lo) : "f"(rb), "f"(ra));
}

__device__ __forceinline__ void ldm_x4(uint32_t* r, uint32_t addr) {
    asm volatile("ldmatrix.sync.aligned.m8n8.x4.shared.b16 {%0,%1,%2,%3}, [%4];"
                 : "=r"(r[0]), "=r"(r[1]), "=r"(r[2]), "=r"(r[3]) : "r"(addr));
}

__device__ __forceinline__ void mma_bf16(float* d, const uint32_t* a,
                                         uint32_t b0, uint32_t b1) {
    asm volatile(
        "mma.sync.aligned.m16n8k16.row.col.f32.bf16.bf16.f32 "
        "{%0,%1,%2,%3},{%4,%5,%6,%7},{%8,%9},{%0,%1,%2,%3};"
        : "+f"(d[0]), "+f"(d[1]), "+f"(d[2]), "+f"(d[3])
        : "r"(a[0]), "r"(a[1]), "r"(a[2]), "r"(a[3]), "r"(b0), "r"(b1));
}

#define CP16(d, s)  asm volatile("cp.async.cg.shared.global [%0], [%1], 16;" \
                                 :: "r"(d), "l"(s) : "memory")
#define CPCOMMIT()  asm volatile("cp.async.commit_group;" ::: "memory")
#define CPWAIT1()   asm volatile("cp.async.wait_group 1;" ::: "memory")

// =============== split prep: fp32 -> bf16 hi/lo arrays ====================
struct SplitTable {
    const float* src[13];
    uint32_t*    hi [13];
    uint32_t*    lo [13];
    int          cum[14];   // cumulative block counts
};

__global__ __launch_bounds__(256) void split_all(SplitTable t)
{
    const int bx = blockIdx.x;
    int e = 0;
#pragma unroll
    for (int i = 1; i < 13; i++) if (bx >= t.cum[i]) e = i;
    const int idx4 = (bx - t.cum[e]) * 256 + threadIdx.x;  // float4 index
    float4 v = reinterpret_cast<const float4*>(t.src[e])[idx4];
    uint32_t h0, l0, h1, l1;
    cvt_pair(v.x, v.y, h0, l0);
    cvt_pair(v.z, v.w, h1, l1);
    reinterpret_cast<uint2*>(t.hi[e])[idx4] = make_uint2(h0, h1);
    reinterpret_cast<uint2*>(t.lo[e])[idx4] = make_uint2(l0, l1);
}

// =============== batched tensor-core GEMM =================================
// C_z[M,N] = A_z[M,K] @ B_z[N,K]^T (+bias)(+relu).
// A, B pre-split bf16 hi/lo in gmem (packed u32 pairs). 3-MMA compensated.
// CTA tile 128x128, Ktile 32, cp.async 2-stage pipeline, 16 warps (4x4).
struct GemmBatch {
    const uint32_t *Ahi[4], *Alo[4], *Bhi[4], *Blo[4];
    const float*    bias[4];
    float*          C[4];
    uint32_t       *Chi[4], *Clo[4];
};

#define SROW       80
#define TILE       (128 * SROW)     // 10240
#define BUF        (4 * TILE)       // 40960
#define GEMM_SMEM  (2 * BUF)        // 81920

__global__ void __launch_bounds__(512, 1)
gemm_mma(GemmBatch args, int N, int K, int relu, int osplit)
{
    extern __shared__ char smem[];
    const int z    = blockIdx.z;
    const int tid  = threadIdx.x;
    const int lane = tid & 31;
    const int wid  = tid >> 5;
    const int wm   = wid & 3;       // warp row (4)
    const int wn   = wid >> 2;      // warp col (4)
    const uint32_t sbase = smem_u32(smem);

    // loader: each thread owns one 16B chunk per tile (row, kc)
    const int row = tid >> 2;
    const int kc  = tid & 3;
    const char* srcAh = (const char*)args.Ahi[z] + ((size_t)(blockIdx.y * 128 + row) * K + kc * 8) * 2;
    const char* srcAl = (const char*)args.Alo[z] + ((size_t)(blockIdx.y * 128 + row) * K + kc * 8) * 2;
    const char* srcBh = (const char*)args.Bhi[z] + ((size_t)(blockIdx.x * 128 + row) * K + kc * 8) * 2;
    const char* srcBl = (const char*)args.Blo[z] + ((size_t)(blockIdx.x * 128 + row) * K + kc * 8) * 2;
    const uint32_t dstb = sbase + row * SROW + kc * 16;

    float acc[2][4][4];
#pragma unroll
    for (int a = 0; a < 2; a++)
#pragma unroll
        for (int b = 0; b < 4; b++)
#pragma unroll
            for (int c = 0; c < 4; c++) acc[a][b][c] = 0.f;

    const int nk = K >> 5;

#define ISSUE(kt, b) do {                                    \
        const uint32_t _d = dstb + (b) * BUF;                \
        const size_t _o = (size_t)(kt) * 64;                 \
        CP16(_d,            srcAh + _o);                     \
        CP16(_d + TILE,     srcAl + _o);                     \
        CP16(_d + 2 * TILE, srcBh + _o);                     \
        CP16(_d + 3 * TILE, srcBl + _o);                     \
    } while (0)

    ISSUE(0, 0); CPCOMMIT();
    ISSUE(1, 1); CPCOMMIT();

    const int lrow  = lane & 15;
    const int khalf = lane >> 4;

    for (int kt = 0; kt < nk; kt++) {
        const int b = kt & 1;
        CPWAIT1();
        __syncthreads();
        const uint32_t sA  = sbase + b * BUF;
        const uint32_t sAl = sA + TILE;
        const uint32_t sB  = sA + 2 * TILE;
        const uint32_t sBl = sA + 3 * TILE;
#pragma unroll
        for (int ks = 0; ks < 2; ks++) {
            const uint32_t koff = ks * 32 + khalf * 16;
            uint32_t ah[2][4], bh[2][4];
#pragma unroll
            for (int mb = 0; mb < 2; mb++)
                ldm_x4(ah[mb], sA + (wm * 32 + mb * 16 + lrow) * SROW + koff);
#pragma unroll
            for (int nbb = 0; nbb < 2; nbb++)
                ldm_x4(bh[nbb], sB + (wn * 32 + nbb * 16 + lrow) * SROW + koff);
#pragma unroll
            for (int mb = 0; mb < 2; mb++)
#pragma unroll
                for (int nb = 0; nb < 4; nb++)
                    mma_bf16(acc[mb][nb], ah[mb],
                             bh[nb >> 1][nb & 1], bh[nb >> 1][(nb & 1) + 2]);
            uint32_t bl[2][4];
#pragma unroll
            for (int nbb = 0; nbb < 2; nbb++)
                ldm_x4(bl[nbb], sBl + (wn * 32 + nbb * 16 + lrow) * SROW + koff);
#pragma unroll
            for (int mb = 0; mb < 2; mb++)
#pragma unroll
                for (int nb = 0; nb < 4; nb++)
                    mma_bf16(acc[mb][nb], ah[mb],
                             bl[nb >> 1][nb & 1], bl[nb >> 1][(nb & 1) + 2]);
            uint32_t al[2][4];
#pragma unroll
            for (int mb = 0; mb < 2; mb++)
                ldm_x4(al[mb], sAl + (wm * 32 + mb * 16 + lrow) * SROW + koff);
#pragma unroll
            for (int mb = 0; mb < 2; mb++)
#pragma unroll
                for (int nb = 0; nb < 4; nb++)
                    mma_bf16(acc[mb][nb], al[mb],
                             bh[nb >> 1][nb & 1], bh[nb >> 1][(nb & 1) + 2]);
        }
        __syncthreads();
        if (kt + 2 < nk) ISSUE(kt + 2, b);
        CPCOMMIT();
    }
#undef ISSUE

    // epilogue
    const int r0 = blockIdx.y * 128 + wm * 32 + (lane >> 2);
    const int c0 = blockIdx.x * 128 + wn * 32 + (lane & 3) * 2;
    const float* bias = args.bias[z];
#pragma unroll
    for (int nb = 0; nb < 4; nb++) {
        const int col = c0 + nb * 8;
        const float b0 = bias ? bias[col]     : 0.f;
        const float b1 = bias ? bias[col + 1] : 0.f;
#pragma unroll
        for (int mb = 0; mb < 2; mb++) {
            float v0 = acc[mb][nb][0] + b0;
            float v1 = acc[mb][nb][1] + b1;
            float v2 = acc[mb][nb][2] + b0;
            float v3 = acc[mb][nb][3] + b1;
            if (relu) {
                v0 = fmaxf(v0, 0.f); v1 = fmaxf(v1, 0.f);
                v2 = fmaxf(v2, 0.f); v3 = fmaxf(v3, 0.f);
            }
            const int r = r0 + mb * 16;
            if (!osplit) {
                *reinterpret_cast<float2*>(args.C[z] + (size_t)r * N + col)       = make_float2(v0, v1);
                *reinterpret_cast<float2*>(args.C[z] + (size_t)(r + 8) * N + col) = make_float2(v2, v3);
            } else {
                uint32_t hu, lu;
                cvt_pair(v0, v1, hu, lu);
                args.Chi[z][((size_t)r * N + col) >> 1] = hu;
                args.Clo[z][((size_t)r * N + col) >> 1] = lu;
                cvt_pair(v2, v3, hu, lu);
                args.Chi[z][((size_t)(r + 8) * N + col) >> 1] = hu;
                args.Clo[z][((size_t)(r + 8) * N + col) >> 1] = lu;
            }
        }
    }
}

// ---------------- per-row attention (1 CTA per (batch row, param)) --------
// Consumes qkv fp32, writes attn output pre-split (hi/lo bf16).
struct AttnBatch { const float* qkv[4]; uint32_t* ahi[4]; uint32_t* alo[4]; };

__global__ __launch_bounds__(256)
void attn_kernel(AttnBatch args, const int* __restrict__ emask)
{
    __shared__ float Qs[16][64];
    __shared__ float Kt[64][68];
    __shared__ float Vs[64][64];
    __shared__ float Ws[16][68];
    __shared__ int   em[64];

    const int b   = blockIdx.x;
    const int z   = blockIdx.z;
    const int tid = threadIdx.x;
    const float* __restrict__ qkv = args.qkv[z];
    uint32_t* __restrict__ ahi    = args.ahi[z];
    uint32_t* __restrict__ alo    = args.alo[z];

    if (tid < 64) em[tid] = emask[b * 64 + tid];
    const float* qb = qkv + (size_t)b * 64 * 768;

    for (int hh = 0; hh < 4; ++hh) {
        __syncthreads();
        {
            int n  = tid >> 4;
            int d0 = (tid & 15) << 2;
            *reinterpret_cast<float4*>(&Qs[n][d0]) =
                *reinterpret_cast<const float4*>(qb + (size_t)n * 768 + hh * 64 + d0);
        }
        {
            int n  = tid >> 2;
            int d0 = (tid & 3) << 4;
            const float* kr = qb + (size_t)n * 768 + 256 + hh * 64 + d0;
            const float* vr = qb + (size_t)n * 768 + 512 + hh * 64 + d0;
#pragma unroll
            for (int j = 0; j < 4; j++) {
                float4 kv = *reinterpret_cast<const float4*>(kr + j * 4);
                Kt[d0 + j*4 + 0][n] = kv.x; Kt[d0 + j*4 + 1][n] = kv.y;
                Kt[d0 + j*4 + 2][n] = kv.z; Kt[d0 + j*4 + 3][n] = kv.w;
                *reinterpret_cast<float4*>(&Vs[n][d0 + j*4]) =
                    *reinterpret_cast<const float4*>(vr + j * 4);
            }
        }
        __syncthreads();
        {
            int qi = tid >> 4;
            int k0 = (tid & 15) << 2;
            float4 acc = make_float4(0.f, 0.f, 0.f, 0.f);
#pragma unroll 8
            for (int d = 0; d < 64; ++d) {
                float  qv = Qs[qi][d];
                float4 kv = *reinterpret_cast<const float4*>(&Kt[d][k0]);
                acc.x += qv * kv.x; acc.y += qv * kv.y;
                acc.z += qv * kv.z; acc.w += qv * kv.w;
            }
            int   amq  = em[qi];
            float lg[4] = {acc.x, acc.y, acc.z, acc.w};
#pragma unroll
            for (int j = 0; j < 4; j++) {
                int kk = k0 + j;
                bool valid = (amq == 0) && (em[kk] == 0);
                Ws[qi][kk] = valid ? lg[j] * 0.125f : -1e30f;
            }
        }
        __syncthreads();
        {
            int w = tid >> 5, lane = tid & 31;
            for (int r = 0; r < 2; r++) {
                int   qi = w * 2 + r;
                float v0 = Ws[qi][lane], v1 = Ws[qi][lane + 32];
                float m  = fmaxf(v0, v1);
                for (int off = 16; off; off >>= 1)
                    m = fmaxf(m, __shfl_xor_sync(0xffffffffu, m, off));
                float e0 = 0.f, e1 = 0.f, s = 1.f;
                if (m > -1e29f) {
                    e0 = expf(v0 - m); e1 = expf(v1 - m);
                    s = e0 + e1;
                    for (int off = 16; off; off >>= 1)
                        s += __shfl_xor_sync(0xffffffffu, s, off);
                }
                float inv = 1.f / s;
                Ws[qi][lane]      = e0 * inv;
                Ws[qi][lane + 32] = e1 * inv;
            }
        }
        __syncthreads();
        {
            int qi = tid >> 4;
            int d0 = (tid & 15) << 2;
            float4 acc = make_float4(0.f, 0.f, 0.f, 0.f);
#pragma unroll 8
            for (int k = 0; k < 64; k++) {
                float  wv = Ws[qi][k];
                float4 vv = *reinterpret_cast<const float4*>(&Vs[k][d0]);
                acc.x += wv * vv.x; acc.y += wv * vv.y;
                acc.z += wv * vv.z; acc.w += wv * vv.w;
            }
            const size_t e = ((size_t)b * 16 + qi) * 256 + hh * 64 + d0;
            uint32_t h0, l0, h1, l1;
            cvt_pair(acc.x, acc.y, h0, l0);
            cvt_pair(acc.z, acc.w, h1, l1);
            *reinterpret_cast<uint2*>(ahi + (e >> 1)) = make_uint2(h0, h1);
            *reinterpret_cast<uint2*>(alo + (e >> 1)) = make_uint2(l0, l1);
        }
    }
}

// --------- fc2 + agent-mask + mode reduction (z = mode = param set) -------
struct Fc2Batch { const float* a2[4]; const float* w[4]; const float* bvec[4]; };

__global__ __launch_bounds__(256)
void fc2_reduce(Fc2Batch args, const int* __restrict__ emask)
{
    __shared__ float a2s[16][260];
    __shared__ float red[32][17];
    __shared__ float vecs[32];
    const int b    = blockIdx.x;
    const int mode = blockIdx.z;
    const int tid  = threadIdx.x;
    const float* __restrict__ a2   = args.a2[mode];
    const float* __restrict__ fc2w = args.w[mode];
    const float* __restrict__ fc2b = args.bvec[mode];

    for (int i = tid; i < 1024; i += 256) {
        int a  = i >> 6;
        int c4 = (i & 63) << 2;
        *reinterpret_cast<float4*>(&a2s[a][c4]) =
            *reinterpret_cast<const float4*>(a2 + ((size_t)b * 16 + a) * 256 + c4);
    }
    __syncthreads();

    float x3v[2];
#pragma unroll
    for (int it = 0; it < 2; ++it) {
        int o = tid + it * 256;
        int a = o & 15;
        int e = o >> 4;
        float s = 0.f;
        if (emask[b * 64 + a] == 0) {
            const float* wr = fc2w + e * 256;
            float acc = 0.f;
#pragma unroll 4
            for (int kk = 0; kk < 256; ++kk) acc += a2s[a][kk] * wr[kk];
            s = acc + fc2b[e];
        }
        x3v[it] = s;
        if (mode == 0)
            g_w1mat[((size_t)b * 16 + a) * 32 + e] = fabsf(s);
    }
    if (mode != 0) {
#pragma unroll
        for (int it = 0; it < 2; ++it) {
            int o = tid + it * 256;
            red[o >> 4][o & 15] = x3v[it];
        }
        __syncthreads();
        if (tid < 32) {
            float s = 0.f;
#pragma unroll
            for (int a = 0; a < 16; a++) s += red[tid][a];
            s *= (1.f / 16.f);
            vecs[tid] = s;
            if (mode == 1)      g_b1vec[b * 32 + tid] = s;
            else if (mode == 2) g_wfvec[b * 32 + tid] = s;
        }
        __syncthreads();
        if (mode == 3 && tid == 0) {
            float s = 0.f;
            for (int e = 0; e < 32; e++) s += vecs[e];
            g_vvs[b] = s * (1.f / 32.f);
        }
    }
}

// ---------------- final mixing: 1 warp per batch row ----------------------
__global__ __launch_bounds__(256)
void mix_kernel(const float* __restrict__ qs, float* __restrict__ out)
{
    int tid = threadIdx.x;
    int b   = blockIdx.x * 8 + (tid >> 5);
    int e   = tid & 31;
    float h = g_b1vec[b * 32 + e];
#pragma unroll
    for (int a = 0; a < 16; a++)
        h += qs[b * 16 + a] * fabsf(g_w1mat[((size_t)b * 16 + a) * 32 + e]);
    h = h > 0.f ? h : expm1f(h);
    float val = h * fabsf(g_wfvec[b * 32 + e]);
    for (int off = 16; off; off >>= 1)
        val += __shfl_xor_sync(0xffffffffu, val, off);
    if (e == 0) out[b] = val + g_vvs[b];
}

// ---------------- launch --------------------------------------------------
extern "C" void kernel_launch(void* const* d_in, const int* in_sizes, int n_in,
                              void* d_out, int out_size)
{
    (void)in_sizes; (void)n_in; (void)out_size;
    const float* qs    = (const float*)d_in[0];
    const float* ents  = (const float*)d_in[1];
    const int*   emask = (const int*)d_in[2];

    uint32_t *ehi, *elo, *whi, *wlo, *x1h, *x1l, *ath, *atl;
    float *qkv, *a2;
    cudaGetSymbolAddress((void**)&ehi, g_ehi);
    cudaGetSymbolAddress((void**)&elo, g_elo);
    cudaGetSymbolAddress((void**)&whi, g_whi);
    cudaGetSymbolAddress((void**)&wlo, g_wlo);
    cudaGetSymbolAddress((void**)&x1h, g_x1h);
    cudaGetSymbolAddress((void**)&x1l, g_x1l);
    cudaGetSymbolAddress((void**)&ath, g_ath);
    cudaGetSymbolAddress((void**)&atl, g_atl);
    cudaGetSymbolAddress((void**)&qkv, g_qkv);
    cudaGetSymbolAddress((void**)&a2,  g_a2);

    cudaFuncSetAttribute(gemm_mma, cudaFuncAttributeMaxDynamicSharedMemorySize, GEMM_SMEM);

    // ---- split table: entities + 12 weight matrices ----
    // weight pool layout per param: fc1w(32768) qkvw(196608) outw(65536)
    SplitTable st;
    GemmBatch g1, g2, g3;
    AttnBatch ab;
    Fc2Batch  fb;

    st.src[0] = ents; st.hi[0] = ehi; st.lo[0] = elo;
    int cum = 0;
    st.cum[0] = 0;
    cum += 8192; st.cum[1] = cum;                      // entities: 8.4M elems
    const int wsz[3]  = { 32768, 196608, 65536 };
    const int wblk[3] = { 32, 192, 64 };
    for (int p = 0; p < 4; p++) {
        const float* fc1w = (const float*)d_in[3 + 7*p + 0];
        const float* fc1b = (const float*)d_in[3 + 7*p + 1];
        const float* qkvw = (const float*)d_in[3 + 7*p + 2];
        const float* outw = (const float*)d_in[3 + 7*p + 3];
        const float* outb = (const float*)d_in[3 + 7*p + 4];
        const float* fc2w = (const float*)d_in[3 + 7*p + 5];
        const float* fc2b = (const float*)d_in[3 + 7*p + 6];

        const size_t wbase = (size_t)p * 294912;       // elements
        const float* wsrc[3] = { fc1w, qkvw, outw };
        size_t off = wbase;
        for (int j = 0; j < 3; j++) {
            int e = 1 + p * 3 + j;
            st.src[e] = wsrc[j];
            st.hi[e]  = whi + (off >> 1);
            st.lo[e]  = wlo + (off >> 1);
            cum += wblk[j]; st.cum[e + 1] = cum;
            off += wsz[j];
        }

        uint32_t* fc1w_h = whi + (wbase >> 1);
        uint32_t* fc1w_l = wlo + (wbase >> 1);
        uint32_t* qkvw_h = whi + ((wbase + 32768) >> 1);
        uint32_t* qkvw_l = wlo + ((wbase + 32768) >> 1);
        uint32_t* outw_h = whi + ((wbase + 229376) >> 1);
        uint32_t* outw_l = wlo + ((wbase + 229376) >> 1);

        uint32_t* x1hp = x1h + (size_t)p * 8388608;
        uint32_t* x1lp = x1l + (size_t)p * 8388608;
        uint32_t* athp = ath + (size_t)p * 2097152;
        uint32_t* atlp = atl + (size_t)p * 2097152;
        float*    qkvp = qkv + (size_t)p * 50331648;
        float*    a2p  = a2  + (size_t)p * 4194304;

        // fc1: A = entities split, B = fc1w split, out split -> x1
        g1.Ahi[p] = ehi;  g1.Alo[p] = elo;
        g1.Bhi[p] = fc1w_h; g1.Blo[p] = fc1w_l;
        g1.bias[p] = fc1b; g1.C[p] = nullptr;
        g1.Chi[p] = x1hp; g1.Clo[p] = x1lp;
        // qkv: A = x1 split, B = qkvw split, out fp32
        g2.Ahi[p] = x1hp; g2.Alo[p] = x1lp;
        g2.Bhi[p] = qkvw_h; g2.Blo[p] = qkvw_l;
        g2.bias[p] = nullptr; g2.C[p] = qkvp;
        g2.Chi[p] = nullptr; g2.Clo[p] = nullptr;
        // out-proj: A = attn split, B = outw split, out fp32
        g3.Ahi[p] = athp; g3.Alo[p] = atlp;
        g3.Bhi[p] = outw_h; g3.Blo[p] = outw_l;
        g3.bias[p] = outb; g3.C[p] = a2p;
        g3.Chi[p] = nullptr; g3.Clo[p] = nullptr;

        ab.qkv[p] = qkvp; ab.ahi[p] = athp; ab.alo[p] = atlp;
        fb.a2[p] = a2p;   fb.w[p] = fc2w;   fb.bvec[p] = fc2b;
    }

    // prep: split entities + all weights to bf16 hi/lo
    split_all<<<cum, 256>>>(st);
    // fc1:  x1 = relu(E @ fc1^T + b)   [65536, 256], K=128
    gemm_mma<<<dim3(2, 512, 4), 512, GEMM_SMEM>>>(g1, 256, 128, 1, 1);
    // qkv = x1 @ qkv_w^T               [65536, 768], K=256
    gemm_mma<<<dim3(6, 512, 4), 512, GEMM_SMEM>>>(g2, 768, 256, 0, 0);
    // attention -> split attn           [16384, 256] per param
    attn_kernel<<<dim3(NB, 1, 4), 256>>>(ab, emask);
    // a2 = attn @ out_w^T + out_b       [16384, 256], K=256
    gemm_mma<<<dim3(2, 128, 4), 512, GEMM_SMEM>>>(g3, 256, 256, 0, 0);
    // fc2 + mask + mode reductions
    fc2_reduce<<<dim3(NB, 1, 4), 256>>>(fb, emask);
    mix_kernel<<<NB / 8, 256>>>(qs, (float*)d_out);
}